// round 16
// baseline (speedup 1.0000x reference)
#include <cuda_runtime.h>
#include <cuda_bf16.h>
#include <cstdint>

#define MEM_C 256
#define B_C 20000
#define DIV_C 8
#define N_NODES_C 100000

// Stage layout (bytes): bf16 tiles, 80B row stride (64B data + 16 pad)
#define ST_A_HI 0
#define ST_A_LO 10240
#define ST_B_HI 20480
#define ST_B_LO 30720
#define ST_SIZE 40960
#define SM_SROW 81920
#define SM_TOTAL (81920 + 640)

// Scratch (device globals: allocation-free per harness rules)
__device__ float    g_IC[DIV_C * (long long)B_C * 512];
__device__ float    g_ID[(long long)B_C * 512];
__device__ int      g_IDS[DIV_C * B_C];
__device__ uint16_t g_MSGhi[DIV_C * (long long)B_C * MEM_C];
__device__ uint16_t g_MSGlo[DIV_C * (long long)B_C * MEM_C];
__device__ uint16_t g_MEMhi[(long long)N_NODES_C * MEM_C];
__device__ uint16_t g_MEMlo[(long long)N_NODES_C * MEM_C];
__device__ uint16_t g_DThi[(long long)B_C * MEM_C];
__device__ uint16_t g_DTlo[(long long)B_C * MEM_C];
__device__ uint16_t g_WChi[512 * MEM_C], g_WClo[512 * MEM_C];
__device__ uint16_t g_WDhi[512 * MEM_C], g_WDlo[512 * MEM_C];
__device__ uint16_t g_Whhi[1024 * MEM_C], g_Whlo[1024 * MEM_C];

__device__ __forceinline__ uint32_t smem_u32(const void* p) {
    uint32_t a;
    asm("{ .reg .u64 t; cvta.to.shared.u64 t, %1; cvt.u32.u64 %0, t; }" : "=r"(a) : "l"(p));
    return a;
}

#define LDM4(r0, r1, r2, r3, addr)                                          \
    asm volatile("ldmatrix.sync.aligned.m8n8.x4.shared.b16 {%0,%1,%2,%3}, [%4];" \
                 : "=r"(r0), "=r"(r1), "=r"(r2), "=r"(r3) : "r"(addr))

// Non-volatile: pure register op, lets ptxas schedule HMMAs freely.
#define MMA_BF16(c, a, b)                                                   \
    asm("mma.sync.aligned.m16n8k16.row.col.f32.bf16.bf16.f32 "              \
        "{%0,%1,%2,%3},{%4,%5,%6,%7},{%8,%9},{%0,%1,%2,%3};"                \
        : "+f"((c)[0]), "+f"((c)[1]), "+f"((c)[2]), "+f"((c)[3])            \
        : "r"((a)[0]), "r"((a)[1]), "r"((a)[2]), "r"((a)[3]),               \
          "r"((b)[0]), "r"((b)[1]))

#define CP16(dst, src)                                                      \
    asm volatile("cp.async.cg.shared.global [%0], [%1], 16;"                \
                 :: "r"(dst), "l"(src))
#define CP_COMMIT() asm volatile("cp.async.commit_group;" ::: "memory")
#define CP_WAIT0()  asm volatile("cp.async.wait_group 0;" ::: "memory")

__global__ void normalize_ids(const unsigned int* __restrict__ raw,
                              int* __restrict__ out, int n)
{
    const bool is64 = (raw[1] == 0u) && (raw[3] == 0u);
    int t = blockIdx.x * blockDim.x + threadIdx.x;
    if (t < n) out[t] = is64 ? (int)raw[2 * t] : (int)raw[t];
}

// fp32 -> bf16 hi/lo split, vectorized float4 per thread
__device__ __forceinline__ void split4(float4 v, uint2& h, uint2& l)
{
    __nv_bfloat162 h01 = __floats2bfloat162_rn(v.x, v.y);
    __nv_bfloat162 h23 = __floats2bfloat162_rn(v.z, v.w);
    float rx = v.x - __bfloat162float(__low2bfloat16(h01));
    float ry = v.y - __bfloat162float(__high2bfloat16(h01));
    float rz = v.z - __bfloat162float(__low2bfloat16(h23));
    float rw = v.w - __bfloat162float(__high2bfloat16(h23));
    __nv_bfloat162 l01 = __floats2bfloat162_rn(rx, ry);
    __nv_bfloat162 l23 = __floats2bfloat162_rn(rz, rw);
    h = make_uint2(*(uint32_t*)&h01, *(uint32_t*)&h23);
    l = make_uint2(*(uint32_t*)&l01, *(uint32_t*)&l23);
}

__global__ void cvt_split(const float* __restrict__ src, uint16_t* __restrict__ hi,
                          uint16_t* __restrict__ lo, long long n4)
{
    long long t = (long long)blockIdx.x * blockDim.x + threadIdx.x;
    if (t >= n4) return;
    uint2 h, l;
    split4(reinterpret_cast<const float4*>(src)[t], h, l);
    reinterpret_cast<uint2*>(hi)[t] = h;
    reinterpret_cast<uint2*>(lo)[t] = l;
}

// Gather-convert B_C rows (compact output)
__global__ void cvt_gather(const float* __restrict__ src, const int* __restrict__ ids,
                           uint16_t* __restrict__ hi, uint16_t* __restrict__ lo)
{
    int t = blockIdx.x * blockDim.x + threadIdx.x;
    if (t >= B_C * 64) return;
    int b = t >> 6, q = t & 63;
    uint2 h, l;
    split4(*(const float4*)(src + (long long)ids[b] * MEM_C + q * 4), h, l);
    reinterpret_cast<uint2*>(hi)[(long long)b * 64 + q] = h;
    reinterpret_cast<uint2*>(lo)[(long long)b * 64 + q] = l;
}

// Refresh bf16 hi/lo mirror for the rows updated by a step (in-place offsets).
__global__ void refresh_rows(const float* __restrict__ mem, const int* __restrict__ ids,
                             uint16_t* __restrict__ hi, uint16_t* __restrict__ lo)
{
    int t = blockIdx.x * blockDim.x + threadIdx.x;
    if (t >= B_C * 64) return;
    int b = t >> 6, q = t & 63;
    long long off = (long long)ids[b] * MEM_C + q * 4;
    uint2 h, l;
    split4(*(const float4*)(mem + off), h, l);
    *(uint2*)(hi + off) = h;
    *(uint2*)(lo + off) = l;
}

// ---------------------------------------------------------------------------
// Unified mma.sync bf16-split GEMM engine, cp.async double-buffered,
// SINGLE __syncthreads() per k-chunk (wait0 -> sync -> issue -> MMA).
// CTA tile: 128 gathered rows x 128 W-rows; 2x4 warps, 64x32 warp tile.
// Slice-interleaved W mapping (8-row granularity) enables a fragment-direct
// register epilogue (no smem staging, no post-loop barrier).
// MODE 0: C = D + bias (quarters contiguous)       (IC / ID precompute)
// MODE 1: regular step (gate/tanh interleaved), in-place fp32 mem update
// MODE 2: final step (4 slices interleaved), in-place update
// ---------------------------------------------------------------------------
template<int MODE>
__global__ __launch_bounds__(256, 2)
void mma_gemm(const uint16_t* __restrict__ Ahi, const uint16_t* __restrict__ Alo,
              const int* __restrict__ ids, int M,
              const uint16_t* __restrict__ Whi, const uint16_t* __restrict__ Wlo,
              const float* __restrict__ bias,
              const float* __restrict__ X, const float* __restrict__ Y,
              float* __restrict__ C, float* __restrict__ memv)
{
    extern __shared__ __align__(16) char smem[];
    const int tid = threadIdx.x, lane = tid & 31, wid = tid >> 5;
    const int g = blockIdx.x, row0 = blockIdx.y * 128;

    int r0q, r1q, r2q, r3q;
    if (MODE == 0) { r0q = 64*g; r1q = r0q + 32; r2q = 256 + 64*g; r3q = r2q + 32; }

    int* srow = (int*)(smem + SM_SROW);
    if (tid < 128) {
        int gr = row0 + tid;
        if (gr >= M) gr = M - 1;
        srow[tid] = ids ? ids[gr] : gr;
    }
    __syncthreads();

    // cp.async loader mapping
    const int quad = tid & 3;
    const int rA0 = tid >> 2;          // rows 0..63
    const int rA1 = 64 + (tid >> 2);   // rows 64..127
    const uint32_t sb = smem_u32(smem);

    auto wrow_of = [&](int r) -> int {
        if (MODE == 0) {
            int q = r >> 5;
            return (q == 0 ? r0q : q == 1 ? r1q : q == 2 ? r2q : r3q) + (r & 31);
        } else if (MODE == 1) {
            return (((r & 15) < 8) ? 256 : 768) + 64*g + 8*(r >> 4) + (r & 7);
        } else {
            return ((r >> 3) & 3) * 256 + 32*g + 8*(r >> 5) + (r & 7);
        }
    };
    const uint16_t* a0h = Ahi + (long long)srow[rA0] * MEM_C + quad * 8;
    const uint16_t* a0l = Alo + (long long)srow[rA0] * MEM_C + quad * 8;
    const uint16_t* a1h = Ahi + (long long)srow[rA1] * MEM_C + quad * 8;
    const uint16_t* a1l = Alo + (long long)srow[rA1] * MEM_C + quad * 8;
    const uint16_t* b0h = Whi + (long long)wrow_of(rA0) * MEM_C + quad * 8;
    const uint16_t* b0l = Wlo + (long long)wrow_of(rA0) * MEM_C + quad * 8;
    const uint16_t* b1h = Whi + (long long)wrow_of(rA1) * MEM_C + quad * 8;
    const uint16_t* b1l = Wlo + (long long)wrow_of(rA1) * MEM_C + quad * 8;
    const uint32_t dA0 = sb + ST_A_HI + rA0 * 80 + quad * 16;
    const uint32_t dA1 = sb + ST_A_HI + rA1 * 80 + quad * 16;
    const uint32_t dB0 = sb + ST_B_HI + rA0 * 80 + quad * 16;
    const uint32_t dB1 = sb + ST_B_HI + rA1 * 80 + quad * 16;

    // ldmatrix lane bases
    const int wm = wid >> 2, wn = wid & 3;
    const uint32_t aoff = sb + ST_A_HI +
        (64*wm + (lane & 7) + 8*((lane >> 3) & 1)) * 80 + (lane >> 4) * 16;
    const uint32_t boff0 = sb + ST_B_HI +
        (32*wn + (lane & 7) + (lane >> 4) * 8) * 80 + ((lane >> 3) & 1) * 16;
    const uint32_t boff1 = boff0 + 16 * 80;

    float acc[4][4][4];
#pragma unroll
    for (int i = 0; i < 4; ++i)
#pragma unroll
        for (int j = 0; j < 4; ++j)
#pragma unroll
            for (int e = 0; e < 4; ++e) acc[i][j][e] = 0.0f;

    auto issue = [&](int kb, uint32_t so) {
        CP16(dA0 + so,             a0h + kb);
        CP16(dA0 + so + 10240,     a0l + kb);
        CP16(dA1 + so,             a1h + kb);
        CP16(dA1 + so + 10240,     a1l + kb);
        CP16(dB0 + so,             b0h + kb);
        CP16(dB0 + so + 10240,     b0l + kb);
        CP16(dB1 + so,             b1h + kb);
        CP16(dB1 + so + 10240,     b1l + kb);
    };

    issue(0, 0);
    CP_COMMIT();

#pragma unroll 1
    for (int kc = 0; kc < 8; ++kc) {
        const uint32_t so = (uint32_t)(kc & 1) * ST_SIZE;
        CP_WAIT0();
        __syncthreads();   // single barrier per chunk: data visible + WAR safe
        if (kc < 7) {
            issue((kc + 1) * 32, (uint32_t)((kc + 1) & 1) * ST_SIZE);
            CP_COMMIT();
        }
#pragma unroll
        for (int kk = 0; kk < 2; ++kk) {
            uint32_t ka  = aoff  + so + kk * 32;
            uint32_t kb0 = boff0 + so + kk * 32;
            uint32_t kb1 = boff1 + so + kk * 32;
            uint32_t ah[4][4], al[4][4], bh[4][2], bl[4][2];
#pragma unroll
            for (int tm = 0; tm < 4; ++tm) {
                LDM4(ah[tm][0], ah[tm][1], ah[tm][2], ah[tm][3], ka + tm * 1280);
                LDM4(al[tm][0], al[tm][1], al[tm][2], al[tm][3], ka + tm * 1280 + 10240);
            }
            LDM4(bh[0][0], bh[0][1], bh[1][0], bh[1][1], kb0);
            LDM4(bh[2][0], bh[2][1], bh[3][0], bh[3][1], kb1);
            LDM4(bl[0][0], bl[0][1], bl[1][0], bl[1][1], kb0 + 10240);
            LDM4(bl[2][0], bl[2][1], bl[3][0], bl[3][1], kb1 + 10240);
            // Term-major; per-acc add order hh, hl, lh (numerics fixed).
#pragma unroll
            for (int tm = 0; tm < 4; ++tm)
#pragma unroll
                for (int tn = 0; tn < 4; ++tn)
                    MMA_BF16(acc[tm][tn], ah[tm], bh[tn]);
#pragma unroll
            for (int tm = 0; tm < 4; ++tm)
#pragma unroll
                for (int tn = 0; tn < 4; ++tn)
                    MMA_BF16(acc[tm][tn], ah[tm], bl[tn]);
#pragma unroll
            for (int tm = 0; tm < 4; ++tm)
#pragma unroll
                for (int tn = 0; tn < 4; ++tn)
                    MMA_BF16(acc[tm][tn], al[tm], bh[tn]);
        }
    }

    // ---- Fragment-direct epilogue (no smem staging, no barrier) ----
    const int lr  = lane >> 2;
    const int lc2 = 2 * (lane & 3);
#pragma unroll
    for (int tm = 0; tm < 4; ++tm) {
#pragma unroll
        for (int h = 0; h < 2; ++h) {
            const int rloc = 64*wm + 16*tm + lr + 8*h;
            const int gb = row0 + rloc;
            if (gb >= M) continue;
            if (MODE == 0) {
                float* crow = C + (long long)gb * 512;
#pragma unroll
                for (int tn = 0; tn < 4; ++tn) {
                    int cc = 32*wn + 8*tn + lc2;
                    int qs = cc >> 5;
                    int ob = (qs==0?r0q:qs==1?r1q:qs==2?r2q:r3q) + (cc & 31);
                    float2 bv = *(const float2*)(bias + ob);
                    float2 o = make_float2(acc[tm][tn][2*h]   + bv.x,
                                           acc[tm][tn][2*h+1] + bv.y);
                    *(float2*)(crow + ob) = o;
                }
            } else if (MODE == 1) {
                int nid = srow[rloc];
                const float* xr = X + (long long)gb * 512;
                float* mr = memv + (long long)nid * 256;
#pragma unroll
                for (int ps = 0; ps < 2; ++ps) {
                    int col  = 16*wn + 8*ps + lc2;   // 0..62
                    int base = 64*g + col;
                    float2 bg = *(const float2*)(bias + 256 + base);
                    float2 bt = *(const float2*)(bias + 768 + base);
                    float2 xg = *(const float2*)(xr + base);
                    float2 xt = *(const float2*)(xr + 256 + base);
                    float2 mg = *(const float2*)(mr + base);
                    float gg0 = 1.0f/(1.0f+__expf(-(xg.x + acc[tm][2*ps][2*h]   + bg.x)));
                    float tt0 = tanhf(xt.x + acc[tm][2*ps+1][2*h]   + bt.x);
                    float gg1 = 1.0f/(1.0f+__expf(-(xg.y + acc[tm][2*ps][2*h+1] + bg.y)));
                    float tt1 = tanhf(xt.y + acc[tm][2*ps+1][2*h+1] + bt.y);
                    float2 o = make_float2((1.0f-gg0)*tt0 + gg0*mg.x,
                                           (1.0f-gg1)*tt1 + gg1*mg.y);
                    *(float2*)(mr + base) = o;
                }
            } else {
                int nid = srow[rloc];
                const float* xr = X + (long long)gb * 512;
                const float* yr = Y + (long long)gb * 512;
                float* mr = memv + (long long)nid * 256;
                int col  = 8*wn + lc2;               // 0..30
                int base = 32*g + col;
                float2 b0 = *(const float2*)(bias + base);
                float2 b1 = *(const float2*)(bias + 256 + base);
                float2 b2 = *(const float2*)(bias + 512 + base);
                float2 b3 = *(const float2*)(bias + 768 + base);
                float2 icg = *(const float2*)(xr + base);
                float2 ich = *(const float2*)(xr + 256 + base);
                float2 idg = *(const float2*)(yr + base);
                float2 idh = *(const float2*)(yr + 256 + base);
                float2 mg = *(const float2*)(mr + base);
                float o[2];
#pragma unroll
                for (int e = 0; e < 2; ++e) {
                    float GD = 1.0f/(1.0f+__expf(-(((const float*)&idg)[e]
                                 + acc[tm][0][2*h+e] + ((const float*)&b0)[e])));
                    float GC = 1.0f/(1.0f+__expf(-(((const float*)&icg)[e]
                                 + acc[tm][1][2*h+e] + ((const float*)&b1)[e])));
                    float hD = tanhf(((const float*)&idh)[e]
                                 + acc[tm][2][2*h+e] + ((const float*)&b2)[e]);
                    float hC = tanhf(((const float*)&ich)[e]
                                 + acc[tm][3][2*h+e] + ((const float*)&b3)[e]);
                    float m = ((const float*)&mg)[e];
                    o[e] = 0.5f*(GD*hD + GC*hC + (2.0f - GD - GC)*m);
                }
                *(float2*)(mr + base) = make_float2(o[0], o[1]);
            }
        }
    }
}

// ---------------------------------------------------------------------------
extern "C" void kernel_launch(void* const* d_in, const int* in_sizes, int n_in,
                              void* d_out, int out_size)
{
    const float* memory   = (const float*)d_in[0];
    const void*  node_raw = d_in[1];
    const float* messages = (const float*)d_in[2];
    const float* dtdg     = (const float*)d_in[3];
    const float* WCw      = (const float*)d_in[4];
    const float* WCb      = (const float*)d_in[5];
    const float* WDw      = (const float*)d_in[6];
    const float* WDb      = (const float*)d_in[7];
    const float* Whw      = (const float*)d_in[8];
    const float* Whb      = (const float*)d_in[9];
    float* mem = (float*)d_out;

    float *IC, *IDb; int *IDS;
    uint16_t *MSGhi, *MSGlo, *MEMhi, *MEMlo, *DThi, *DTlo;
    uint16_t *WChi, *WClo, *WDhi, *WDlo, *Whhi, *Whlo;
    cudaGetSymbolAddress((void**)&IC,    g_IC);
    cudaGetSymbolAddress((void**)&IDb,   g_ID);
    cudaGetSymbolAddress((void**)&IDS,   g_IDS);
    cudaGetSymbolAddress((void**)&MSGhi, g_MSGhi);
    cudaGetSymbolAddress((void**)&MSGlo, g_MSGlo);
    cudaGetSymbolAddress((void**)&MEMhi, g_MEMhi);
    cudaGetSymbolAddress((void**)&MEMlo, g_MEMlo);
    cudaGetSymbolAddress((void**)&DThi,  g_DThi);
    cudaGetSymbolAddress((void**)&DTlo,  g_DTlo);
    cudaGetSymbolAddress((void**)&WChi,  g_WChi);
    cudaGetSymbolAddress((void**)&WClo,  g_WClo);
    cudaGetSymbolAddress((void**)&WDhi,  g_WDhi);
    cudaGetSymbolAddress((void**)&WDlo,  g_WDlo);
    cudaGetSymbolAddress((void**)&Whhi,  g_Whhi);
    cudaGetSymbolAddress((void**)&Whlo,  g_Whlo);

    // One-time stream/event setup (same-priority streams).
    static cudaStream_t s2 = nullptr;
    static cudaEvent_t evFork, evID, evIC[DIV_C];
    if (!s2) {
        cudaStreamCreateWithFlags(&s2, cudaStreamNonBlocking);
        cudaEventCreateWithFlags(&evFork, cudaEventDisableTiming);
        cudaEventCreateWithFlags(&evID,   cudaEventDisableTiming);
        for (int i = 0; i < DIV_C; ++i)
            cudaEventCreateWithFlags(&evIC[i], cudaEventDisableTiming);
    }

    cudaFuncSetAttribute(mma_gemm<0>, cudaFuncAttributeMaxDynamicSharedMemorySize, SM_TOTAL);
    cudaFuncSetAttribute(mma_gemm<1>, cudaFuncAttributeMaxDynamicSharedMemorySize, SM_TOTAL);
    cudaFuncSetAttribute(mma_gemm<2>, cudaFuncAttributeMaxDynamicSharedMemorySize, SM_TOTAL);

    const int gy  = (B_C + 127) / 128;  // 157
    const int rfb = (B_C * 64 + 255) / 256;
    const long long n4_mem   = (long long)N_NODES_C * MEM_C / 4;
    const long long n4_slice = (long long)B_C * MEM_C / 4;
    const int* ids7 = IDS + (DIV_C - 1) * B_C;

    // --- Stream 0: ids, WC cvt, msg-slice0 cvt, then IC0 GEMM contention-free
    normalize_ids<<<(DIV_C * B_C + 255) / 256, 256>>>(
        (const unsigned int*)node_raw, IDS, DIV_C * B_C);
    cvt_split<<<(512 * MEM_C / 4 + 255) / 256, 256>>>(
        WCw, WChi, WClo, 512 * MEM_C / 4);
    cudaEventRecord(evFork, 0);          // s2 needs IDS + WChi/WClo
    cudaStreamWaitEvent(s2, evFork, 0);

    cvt_split<<<(int)((n4_slice + 255) / 256), 256>>>(
        messages, MSGhi, MSGlo, n4_slice);          // slice 0 only
    mma_gemm<0><<<dim3(4, gy), 256, SM_TOTAL>>>(    // IC0, in-order with chain
        MSGhi, MSGlo, nullptr, B_C, WChi, WClo, WCb,
        nullptr, nullptr, IC, nullptr);

    // --- s2: msg slices 1..7 cvt (contiguous), IC1..7, WD cvt, ID ---
    {
        const long long ao = (long long)B_C * MEM_C;  // slice-1 offset
        cvt_split<<<(int)((7 * n4_slice + 255) / 256), 256, 0, s2>>>(
            messages + ao, MSGhi + ao, MSGlo + ao, 7 * n4_slice);
    }
    for (int s = 1; s < DIV_C; ++s) {
        const long long ao = (long long)s * B_C * MEM_C;
        mma_gemm<0><<<dim3(4, gy), 256, SM_TOTAL, s2>>>(
            MSGhi + ao, MSGlo + ao, nullptr, B_C, WChi, WClo, WCb,
            nullptr, nullptr, IC + (long long)s * B_C * 512, nullptr);
        cudaEventRecord(evIC[s], s2);
    }
    cvt_split<<<(512 * MEM_C / 4 + 255) / 256, 256, 0, s2>>>(
        WDw, WDhi, WDlo, 512 * MEM_C / 4);
    cvt_gather<<<(B_C * 64 + 255) / 256, 256, 0, s2>>>(dtdg, ids7, DThi, DTlo);
    mma_gemm<0><<<dim3(4, gy), 256, SM_TOTAL, s2>>>(
        DThi, DTlo, nullptr, B_C, WDhi, WDlo, WDb,
        nullptr, nullptr, IDb, nullptr);
    cudaEventRecord(evID, s2);

    // --- Stream 0: remaining chain prerequisites (overlap IC0's tail + s2) ---
    cudaMemcpyAsync(mem, memory, (size_t)N_NODES_C * MEM_C * sizeof(float),
                    cudaMemcpyDeviceToDevice);
    cvt_split<<<(int)((n4_mem + 255) / 256), 256>>>(memory, MEMhi, MEMlo, n4_mem);
    cvt_split<<<(1024 * MEM_C / 4 + 255) / 256, 256>>>(
        Whw, Whhi, Whlo, 1024 * MEM_C / 4);

    // --- Stream 0: sequential step chain (IC0 already in-order) ---
    mma_gemm<1><<<dim3(4, gy), 256, SM_TOTAL>>>(
        MEMhi, MEMlo, IDS, B_C, Whhi, Whlo, Whb,
        IC, nullptr, nullptr, mem);
    refresh_rows<<<rfb, 256>>>(mem, IDS, MEMhi, MEMlo);
    for (int s = 1; s < DIV_C - 1; ++s) {
        cudaStreamWaitEvent(0, evIC[s], 0);
        mma_gemm<1><<<dim3(4, gy), 256, SM_TOTAL>>>(
            MEMhi, MEMlo, IDS + s * B_C, B_C, Whhi, Whlo, Whb,
            IC + (long long)s * B_C * 512, nullptr, nullptr, mem);
        refresh_rows<<<rfb, 256>>>(mem, IDS + s * B_C, MEMhi, MEMlo);
    }
    cudaStreamWaitEvent(0, evIC[DIV_C - 1], 0);
    cudaStreamWaitEvent(0, evID, 0);
    mma_gemm<2><<<dim3(8, gy), 256, SM_TOTAL>>>(
        MEMhi, MEMlo, ids7, B_C, Whhi, Whlo, Whb,
        IC + (long long)(DIV_C - 1) * B_C * 512, IDb, nullptr, mem);
}

// round 17
// speedup vs baseline: 1.4520x; 1.4520x over previous
#include <cuda_runtime.h>
#include <cuda_bf16.h>
#include <cstdint>

#define MEM_C 256
#define B_C 20000
#define DIV_C 8
#define N_NODES_C 100000

// Stage layout (bytes): bf16 tiles, 80B row stride (64B data + 16 pad)
#define ST_A_HI 0
#define ST_A_LO 10240
#define ST_B_HI 20480
#define ST_B_LO 30720
#define ST_SIZE 40960
#define SM_SROW 81920
#define SM_TOTAL (81920 + 640)

// Scratch (device globals: allocation-free per harness rules)
__device__ float    g_IC[DIV_C * (long long)B_C * 512];
__device__ float    g_ID[(long long)B_C * 512];
__device__ int      g_IDS[DIV_C * B_C];
__device__ uint16_t g_MSGhi[DIV_C * (long long)B_C * MEM_C];
__device__ uint16_t g_MSGlo[DIV_C * (long long)B_C * MEM_C];
__device__ uint16_t g_MEMhi[(long long)N_NODES_C * MEM_C];
__device__ uint16_t g_MEMlo[(long long)N_NODES_C * MEM_C];
__device__ uint16_t g_DThi[(long long)B_C * MEM_C];
__device__ uint16_t g_DTlo[(long long)B_C * MEM_C];
__device__ uint16_t g_WChi[512 * MEM_C], g_WClo[512 * MEM_C];
__device__ uint16_t g_WDhi[512 * MEM_C], g_WDlo[512 * MEM_C];
__device__ uint16_t g_Whhi[1024 * MEM_C], g_Whlo[1024 * MEM_C];

__device__ __forceinline__ uint32_t smem_u32(const void* p) {
    uint32_t a;
    asm("{ .reg .u64 t; cvta.to.shared.u64 t, %1; cvt.u32.u64 %0, t; }" : "=r"(a) : "l"(p));
    return a;
}

#define LDM4(r0, r1, r2, r3, addr)                                          \
    asm volatile("ldmatrix.sync.aligned.m8n8.x4.shared.b16 {%0,%1,%2,%3}, [%4];" \
                 : "=r"(r0), "=r"(r1), "=r"(r2), "=r"(r3) : "r"(addr))

// Non-volatile: pure register op, lets ptxas schedule HMMAs freely.
#define MMA_BF16(c, a, b)                                                   \
    asm("mma.sync.aligned.m16n8k16.row.col.f32.bf16.bf16.f32 "              \
        "{%0,%1,%2,%3},{%4,%5,%6,%7},{%8,%9},{%0,%1,%2,%3};"                \
        : "+f"((c)[0]), "+f"((c)[1]), "+f"((c)[2]), "+f"((c)[3])            \
        : "r"((a)[0]), "r"((a)[1]), "r"((a)[2]), "r"((a)[3]),               \
          "r"((b)[0]), "r"((b)[1]))

#define CP16(dst, src)                                                      \
    asm volatile("cp.async.cg.shared.global [%0], [%1], 16;"                \
                 :: "r"(dst), "l"(src))
#define CP_COMMIT() asm volatile("cp.async.commit_group;" ::: "memory")
#define CP_WAIT1()  asm volatile("cp.async.wait_group 1;" ::: "memory")
#define CP_WAIT0()  asm volatile("cp.async.wait_group 0;" ::: "memory")

__global__ void normalize_ids(const unsigned int* __restrict__ raw,
                              int* __restrict__ out, int n)
{
    const bool is64 = (raw[1] == 0u) && (raw[3] == 0u);
    int t = blockIdx.x * blockDim.x + threadIdx.x;
    if (t < n) out[t] = is64 ? (int)raw[2 * t] : (int)raw[t];
}

// fp32 -> bf16 hi/lo split, vectorized float4 per thread
__device__ __forceinline__ void split4(float4 v, uint2& h, uint2& l)
{
    __nv_bfloat162 h01 = __floats2bfloat162_rn(v.x, v.y);
    __nv_bfloat162 h23 = __floats2bfloat162_rn(v.z, v.w);
    float rx = v.x - __bfloat162float(__low2bfloat16(h01));
    float ry = v.y - __bfloat162float(__high2bfloat16(h01));
    float rz = v.z - __bfloat162float(__low2bfloat16(h23));
    float rw = v.w - __bfloat162float(__high2bfloat16(h23));
    __nv_bfloat162 l01 = __floats2bfloat162_rn(rx, ry);
    __nv_bfloat162 l23 = __floats2bfloat162_rn(rz, rw);
    h = make_uint2(*(uint32_t*)&h01, *(uint32_t*)&h23);
    l = make_uint2(*(uint32_t*)&l01, *(uint32_t*)&l23);
}

__global__ void cvt_split(const float* __restrict__ src, uint16_t* __restrict__ hi,
                          uint16_t* __restrict__ lo, long long n4)
{
    long long t = (long long)blockIdx.x * blockDim.x + threadIdx.x;
    if (t >= n4) return;
    uint2 h, l;
    split4(reinterpret_cast<const float4*>(src)[t], h, l);
    reinterpret_cast<uint2*>(hi)[t] = h;
    reinterpret_cast<uint2*>(lo)[t] = l;
}

// Gather-convert B_C rows (compact output)
__global__ void cvt_gather(const float* __restrict__ src, const int* __restrict__ ids,
                           uint16_t* __restrict__ hi, uint16_t* __restrict__ lo)
{
    int t = blockIdx.x * blockDim.x + threadIdx.x;
    if (t >= B_C * 64) return;
    int b = t >> 6, q = t & 63;
    uint2 h, l;
    split4(*(const float4*)(src + (long long)ids[b] * MEM_C + q * 4), h, l);
    reinterpret_cast<uint2*>(hi)[(long long)b * 64 + q] = h;
    reinterpret_cast<uint2*>(lo)[(long long)b * 64 + q] = l;
}

// Refresh bf16 hi/lo mirror for the rows updated by a step (in-place offsets).
__global__ void refresh_rows(const float* __restrict__ mem, const int* __restrict__ ids,
                             uint16_t* __restrict__ hi, uint16_t* __restrict__ lo)
{
    int t = blockIdx.x * blockDim.x + threadIdx.x;
    if (t >= B_C * 64) return;
    int b = t >> 6, q = t & 63;
    long long off = (long long)ids[b] * MEM_C + q * 4;
    uint2 h, l;
    split4(*(const float4*)(mem + off), h, l);
    *(uint2*)(hi + off) = h;
    *(uint2*)(lo + off) = l;
}

// ---------------------------------------------------------------------------
// Unified mma.sync bf16-split GEMM engine, cp.async double-buffered
// (R15-proven loop: issue -> commit -> wait_group 1 -> sync -> MMA;
//  two groups in flight). Fragment-direct register epilogue.
// MODE 0: C = D + bias (quarters contiguous)       (IC / ID precompute)
// MODE 1: regular step (gate/tanh interleaved), in-place fp32 mem update
// MODE 2: final step (4 slices interleaved), in-place update
// ---------------------------------------------------------------------------
template<int MODE>
__global__ __launch_bounds__(256, 2)
void mma_gemm(const uint16_t* __restrict__ Ahi, const uint16_t* __restrict__ Alo,
              const int* __restrict__ ids, int M,
              const uint16_t* __restrict__ Whi, const uint16_t* __restrict__ Wlo,
              const float* __restrict__ bias,
              const float* __restrict__ X, const float* __restrict__ Y,
              float* __restrict__ C, float* __restrict__ memv)
{
    extern __shared__ __align__(16) char smem[];
    const int tid = threadIdx.x, lane = tid & 31, wid = tid >> 5;
    const int g = blockIdx.x, row0 = blockIdx.y * 128;

    int r0q, r1q, r2q, r3q;
    if (MODE == 0) { r0q = 64*g; r1q = r0q + 32; r2q = 256 + 64*g; r3q = r2q + 32; }

    int* srow = (int*)(smem + SM_SROW);
    if (tid < 128) {
        int gr = row0 + tid;
        if (gr >= M) gr = M - 1;
        srow[tid] = ids ? ids[gr] : gr;
    }
    __syncthreads();

    // cp.async loader mapping
    const int quad = tid & 3;
    const int rA0 = tid >> 2;          // rows 0..63
    const int rA1 = 64 + (tid >> 2);   // rows 64..127
    const uint32_t sb = smem_u32(smem);

    auto wrow_of = [&](int r) -> int {
        if (MODE == 0) {
            int q = r >> 5;
            return (q == 0 ? r0q : q == 1 ? r1q : q == 2 ? r2q : r3q) + (r & 31);
        } else if (MODE == 1) {
            return (((r & 15) < 8) ? 256 : 768) + 64*g + 8*(r >> 4) + (r & 7);
        } else {
            return ((r >> 3) & 3) * 256 + 32*g + 8*(r >> 5) + (r & 7);
        }
    };
    const uint16_t* a0h = Ahi + (long long)srow[rA0] * MEM_C + quad * 8;
    const uint16_t* a0l = Alo + (long long)srow[rA0] * MEM_C + quad * 8;
    const uint16_t* a1h = Ahi + (long long)srow[rA1] * MEM_C + quad * 8;
    const uint16_t* a1l = Alo + (long long)srow[rA1] * MEM_C + quad * 8;
    const uint16_t* b0h = Whi + (long long)wrow_of(rA0) * MEM_C + quad * 8;
    const uint16_t* b0l = Wlo + (long long)wrow_of(rA0) * MEM_C + quad * 8;
    const uint16_t* b1h = Whi + (long long)wrow_of(rA1) * MEM_C + quad * 8;
    const uint16_t* b1l = Wlo + (long long)wrow_of(rA1) * MEM_C + quad * 8;
    const uint32_t dA0 = sb + ST_A_HI + rA0 * 80 + quad * 16;
    const uint32_t dA1 = sb + ST_A_HI + rA1 * 80 + quad * 16;
    const uint32_t dB0 = sb + ST_B_HI + rA0 * 80 + quad * 16;
    const uint32_t dB1 = sb + ST_B_HI + rA1 * 80 + quad * 16;

    // ldmatrix lane bases
    const int wm = wid >> 2, wn = wid & 3;
    const uint32_t aoff = sb + ST_A_HI +
        (64*wm + (lane & 7) + 8*((lane >> 3) & 1)) * 80 + (lane >> 4) * 16;
    const uint32_t boff0 = sb + ST_B_HI +
        (32*wn + (lane & 7) + (lane >> 4) * 8) * 80 + ((lane >> 3) & 1) * 16;
    const uint32_t boff1 = boff0 + 16 * 80;

    float acc[4][4][4];
#pragma unroll
    for (int i = 0; i < 4; ++i)
#pragma unroll
        for (int j = 0; j < 4; ++j)
#pragma unroll
            for (int e = 0; e < 4; ++e) acc[i][j][e] = 0.0f;

    auto issue = [&](int kb, uint32_t so) {
        CP16(dA0 + so,             a0h + kb);
        CP16(dA0 + so + 10240,     a0l + kb);
        CP16(dA1 + so,             a1h + kb);
        CP16(dA1 + so + 10240,     a1l + kb);
        CP16(dB0 + so,             b0h + kb);
        CP16(dB0 + so + 10240,     b0l + kb);
        CP16(dB1 + so,             b1h + kb);
        CP16(dB1 + so + 10240,     b1l + kb);
    };

    issue(0, 0);
    CP_COMMIT();

#pragma unroll 1
    for (int kc = 0; kc < 8; ++kc) {
        const uint32_t so = (uint32_t)(kc & 1) * ST_SIZE;
        if (kc < 7) {
            issue((kc + 1) * 32, (uint32_t)((kc + 1) & 1) * ST_SIZE);
            CP_COMMIT();
            CP_WAIT1();
        } else {
            CP_WAIT0();
        }
        __syncthreads();
#pragma unroll
        for (int kk = 0; kk < 2; ++kk) {
            uint32_t ka  = aoff  + so + kk * 32;
            uint32_t kb0 = boff0 + so + kk * 32;
            uint32_t kb1 = boff1 + so + kk * 32;
            uint32_t ah[4][4], al[4][4], bh[4][2], bl[4][2];
#pragma unroll
            for (int tm = 0; tm < 4; ++tm) {
                LDM4(ah[tm][0], ah[tm][1], ah[tm][2], ah[tm][3], ka + tm * 1280);
                LDM4(al[tm][0], al[tm][1], al[tm][2], al[tm][3], ka + tm * 1280 + 10240);
            }
            LDM4(bh[0][0], bh[0][1], bh[1][0], bh[1][1], kb0);
            LDM4(bh[2][0], bh[2][1], bh[3][0], bh[3][1], kb1);
            LDM4(bl[0][0], bl[0][1], bl[1][0], bl[1][1], kb0 + 10240);
            LDM4(bl[2][0], bl[2][1], bl[3][0], bl[3][1], kb1 + 10240);
            // Term-major; per-acc add order hh, hl, lh (numerics fixed).
#pragma unroll
            for (int tm = 0; tm < 4; ++tm)
#pragma unroll
                for (int tn = 0; tn < 4; ++tn)
                    MMA_BF16(acc[tm][tn], ah[tm], bh[tn]);
#pragma unroll
            for (int tm = 0; tm < 4; ++tm)
#pragma unroll
                for (int tn = 0; tn < 4; ++tn)
                    MMA_BF16(acc[tm][tn], ah[tm], bl[tn]);
#pragma unroll
            for (int tm = 0; tm < 4; ++tm)
#pragma unroll
                for (int tn = 0; tn < 4; ++tn)
                    MMA_BF16(acc[tm][tn], al[tm], bh[tn]);
        }
        __syncthreads();   // WAR: next issue() targets the buffer just read
    }

    // ---- Fragment-direct epilogue (no smem staging, no barrier) ----
    const int lr  = lane >> 2;
    const int lc2 = 2 * (lane & 3);
#pragma unroll
    for (int tm = 0; tm < 4; ++tm) {
#pragma unroll
        for (int h = 0; h < 2; ++h) {
            const int rloc = 64*wm + 16*tm + lr + 8*h;
            const int gb = row0 + rloc;
            if (gb >= M) continue;
            if (MODE == 0) {
                float* crow = C + (long long)gb * 512;
#pragma unroll
                for (int tn = 0; tn < 4; ++tn) {
                    int cc = 32*wn + 8*tn + lc2;
                    int qs = cc >> 5;
                    int ob = (qs==0?r0q:qs==1?r1q:qs==2?r2q:r3q) + (cc & 31);
                    float2 bv = *(const float2*)(bias + ob);
                    float2 o = make_float2(acc[tm][tn][2*h]   + bv.x,
                                           acc[tm][tn][2*h+1] + bv.y);
                    *(float2*)(crow + ob) = o;
                }
            } else if (MODE == 1) {
                int nid = srow[rloc];
                const float* xr = X + (long long)gb * 512;
                float* mr = memv + (long long)nid * 256;
#pragma unroll
                for (int ps = 0; ps < 2; ++ps) {
                    int col  = 16*wn + 8*ps + lc2;   // 0..62
                    int base = 64*g + col;
                    float2 bg = *(const float2*)(bias + 256 + base);
                    float2 bt = *(const float2*)(bias + 768 + base);
                    float2 xg = *(const float2*)(xr + base);
                    float2 xt = *(const float2*)(xr + 256 + base);
                    float2 mg = *(const float2*)(mr + base);
                    float gg0 = 1.0f/(1.0f+__expf(-(xg.x + acc[tm][2*ps][2*h]   + bg.x)));
                    float tt0 = tanhf(xt.x + acc[tm][2*ps+1][2*h]   + bt.x);
                    float gg1 = 1.0f/(1.0f+__expf(-(xg.y + acc[tm][2*ps][2*h+1] + bg.y)));
                    float tt1 = tanhf(xt.y + acc[tm][2*ps+1][2*h+1] + bt.y);
                    float2 o = make_float2((1.0f-gg0)*tt0 + gg0*mg.x,
                                           (1.0f-gg1)*tt1 + gg1*mg.y);
                    *(float2*)(mr + base) = o;
                }
            } else {
                int nid = srow[rloc];
                const float* xr = X + (long long)gb * 512;
                const float* yr = Y + (long long)gb * 512;
                float* mr = memv + (long long)nid * 256;
                int col  = 8*wn + lc2;               // 0..30
                int base = 32*g + col;
                float2 b0 = *(const float2*)(bias + base);
                float2 b1 = *(const float2*)(bias + 256 + base);
                float2 b2 = *(const float2*)(bias + 512 + base);
                float2 b3 = *(const float2*)(bias + 768 + base);
                float2 icg = *(const float2*)(xr + base);
                float2 ich = *(const float2*)(xr + 256 + base);
                float2 idg = *(const float2*)(yr + base);
                float2 idh = *(const float2*)(yr + 256 + base);
                float2 mg = *(const float2*)(mr + base);
                float o[2];
#pragma unroll
                for (int e = 0; e < 2; ++e) {
                    float GD = 1.0f/(1.0f+__expf(-(((const float*)&idg)[e]
                                 + acc[tm][0][2*h+e] + ((const float*)&b0)[e])));
                    float GC = 1.0f/(1.0f+__expf(-(((const float*)&icg)[e]
                                 + acc[tm][1][2*h+e] + ((const float*)&b1)[e])));
                    float hD = tanhf(((const float*)&idh)[e]
                                 + acc[tm][2][2*h+e] + ((const float*)&b2)[e]);
                    float hC = tanhf(((const float*)&ich)[e]
                                 + acc[tm][3][2*h+e] + ((const float*)&b3)[e]);
                    float m = ((const float*)&mg)[e];
                    o[e] = 0.5f*(GD*hD + GC*hC + (2.0f - GD - GC)*m);
                }
                *(float2*)(mr + base) = make_float2(o[0], o[1]);
            }
        }
    }
}

// ---------------------------------------------------------------------------
extern "C" void kernel_launch(void* const* d_in, const int* in_sizes, int n_in,
                              void* d_out, int out_size)
{
    const float* memory   = (const float*)d_in[0];
    const void*  node_raw = d_in[1];
    const float* messages = (const float*)d_in[2];
    const float* dtdg     = (const float*)d_in[3];
    const float* WCw      = (const float*)d_in[4];
    const float* WCb      = (const float*)d_in[5];
    const float* WDw      = (const float*)d_in[6];
    const float* WDb      = (const float*)d_in[7];
    const float* Whw      = (const float*)d_in[8];
    const float* Whb      = (const float*)d_in[9];
    float* mem = (float*)d_out;

    float *IC, *IDb; int *IDS;
    uint16_t *MSGhi, *MSGlo, *MEMhi, *MEMlo, *DThi, *DTlo;
    uint16_t *WChi, *WClo, *WDhi, *WDlo, *Whhi, *Whlo;
    cudaGetSymbolAddress((void**)&IC,    g_IC);
    cudaGetSymbolAddress((void**)&IDb,   g_ID);
    cudaGetSymbolAddress((void**)&IDS,   g_IDS);
    cudaGetSymbolAddress((void**)&MSGhi, g_MSGhi);
    cudaGetSymbolAddress((void**)&MSGlo, g_MSGlo);
    cudaGetSymbolAddress((void**)&MEMhi, g_MEMhi);
    cudaGetSymbolAddress((void**)&MEMlo, g_MEMlo);
    cudaGetSymbolAddress((void**)&DThi,  g_DThi);
    cudaGetSymbolAddress((void**)&DTlo,  g_DTlo);
    cudaGetSymbolAddress((void**)&WChi,  g_WChi);
    cudaGetSymbolAddress((void**)&WClo,  g_WClo);
    cudaGetSymbolAddress((void**)&WDhi,  g_WDhi);
    cudaGetSymbolAddress((void**)&WDlo,  g_WDlo);
    cudaGetSymbolAddress((void**)&Whhi,  g_Whhi);
    cudaGetSymbolAddress((void**)&Whlo,  g_Whlo);

    // One-time stream/event setup (same-priority streams).
    static cudaStream_t s2 = nullptr, s3 = nullptr;
    static cudaEvent_t evF0, evFork, evPre, evID, evIC[DIV_C];
    if (!s2) {
        cudaStreamCreateWithFlags(&s2, cudaStreamNonBlocking);
        cudaStreamCreateWithFlags(&s3, cudaStreamNonBlocking);
        cudaEventCreateWithFlags(&evF0,   cudaEventDisableTiming);
        cudaEventCreateWithFlags(&evFork, cudaEventDisableTiming);
        cudaEventCreateWithFlags(&evPre,  cudaEventDisableTiming);
        cudaEventCreateWithFlags(&evID,   cudaEventDisableTiming);
        for (int i = 0; i < DIV_C; ++i)
            cudaEventCreateWithFlags(&evIC[i], cudaEventDisableTiming);
    }

    cudaFuncSetAttribute(mma_gemm<0>, cudaFuncAttributeMaxDynamicSharedMemorySize, SM_TOTAL);
    cudaFuncSetAttribute(mma_gemm<1>, cudaFuncAttributeMaxDynamicSharedMemorySize, SM_TOTAL);
    cudaFuncSetAttribute(mma_gemm<2>, cudaFuncAttributeMaxDynamicSharedMemorySize, SM_TOTAL);

    const int gy  = (B_C + 127) / 128;  // 157
    const int rfb = (B_C * 64 + 255) / 256;
    const long long n4_mem   = (long long)N_NODES_C * MEM_C / 4;
    const long long n4_slice = (long long)B_C * MEM_C / 4;
    const int* ids7 = IDS + (DIV_C - 1) * B_C;

    // --- Fork s3 at the very top: chain prerequisites depend only on inputs
    cudaEventRecord(evF0, 0);
    cudaStreamWaitEvent(s3, evF0, 0);
    cudaMemcpyAsync(mem, memory, (size_t)N_NODES_C * MEM_C * sizeof(float),
                    cudaMemcpyDeviceToDevice, s3);
    cvt_split<<<(int)((n4_mem + 255) / 256), 256, 0, s3>>>(memory, MEMhi, MEMlo, n4_mem);
    cvt_split<<<(1024 * MEM_C / 4 + 255) / 256, 256, 0, s3>>>(
        Whw, Whhi, Whlo, 1024 * MEM_C / 4);
    cudaEventRecord(evPre, s3);

    // --- Stream 0: ids, WC cvt, msg-slice0 cvt, then IC0 GEMM ---
    normalize_ids<<<(DIV_C * B_C + 255) / 256, 256>>>(
        (const unsigned int*)node_raw, IDS, DIV_C * B_C);
    cvt_split<<<(512 * MEM_C / 4 + 255) / 256, 256>>>(
        WCw, WChi, WClo, 512 * MEM_C / 4);
    cudaEventRecord(evFork, 0);          // s2 needs IDS + WChi/WClo
    cudaStreamWaitEvent(s2, evFork, 0);

    cvt_split<<<(int)((n4_slice + 255) / 256), 256>>>(
        messages, MSGhi, MSGlo, n4_slice);          // slice 0 only
    mma_gemm<0><<<dim3(4, gy), 256, SM_TOTAL>>>(    // IC0, in-order with chain
        MSGhi, MSGlo, nullptr, B_C, WChi, WClo, WCb,
        nullptr, nullptr, IC, nullptr);

    // --- s2: msg slices 1..7 cvt (contiguous), IC1..7, WD cvt, ID ---
    {
        const long long ao = (long long)B_C * MEM_C;  // slice-1 offset
        cvt_split<<<(int)((7 * n4_slice + 255) / 256), 256, 0, s2>>>(
            messages + ao, MSGhi + ao, MSGlo + ao, 7 * n4_slice);
    }
    for (int s = 1; s < DIV_C; ++s) {
        const long long ao = (long long)s * B_C * MEM_C;
        mma_gemm<0><<<dim3(4, gy), 256, SM_TOTAL, s2>>>(
            MSGhi + ao, MSGlo + ao, nullptr, B_C, WChi, WClo, WCb,
            nullptr, nullptr, IC + (long long)s * B_C * 512, nullptr);
        cudaEventRecord(evIC[s], s2);
    }
    cvt_split<<<(512 * MEM_C / 4 + 255) / 256, 256, 0, s2>>>(
        WDw, WDhi, WDlo, 512 * MEM_C / 4);
    cvt_gather<<<(B_C * 64 + 255) / 256, 256, 0, s2>>>(dtdg, ids7, DThi, DTlo);
    mma_gemm<0><<<dim3(4, gy), 256, SM_TOTAL, s2>>>(
        DThi, DTlo, nullptr, B_C, WDhi, WDlo, WDb,
        nullptr, nullptr, IDb, nullptr);
    cudaEventRecord(evID, s2);

    // --- Stream 0: join prerequisites, then sequential step chain ---
    cudaStreamWaitEvent(0, evPre, 0);
    mma_gemm<1><<<dim3(4, gy), 256, SM_TOTAL>>>(
        MEMhi, MEMlo, IDS, B_C, Whhi, Whlo, Whb,
        IC, nullptr, nullptr, mem);
    refresh_rows<<<rfb, 256>>>(mem, IDS, MEMhi, MEMlo);
    for (int s = 1; s < DIV_C - 1; ++s) {
        cudaStreamWaitEvent(0, evIC[s], 0);
        mma_gemm<1><<<dim3(4, gy), 256, SM_TOTAL>>>(
            MEMhi, MEMlo, IDS + s * B_C, B_C, Whhi, Whlo, Whb,
            IC + (long long)s * B_C * 512, nullptr, nullptr, mem);
        refresh_rows<<<rfb, 256>>>(mem, IDS + s * B_C, MEMhi, MEMlo);
    }
    cudaStreamWaitEvent(0, evIC[DIV_C - 1], 0);
    cudaStreamWaitEvent(0, evID, 0);
    mma_gemm<2><<<dim3(8, gy), 256, SM_TOTAL>>>(
        MEMhi, MEMlo, ids7, B_C, Whhi, Whlo, Whb,
        IC + (long long)(DIV_C - 1) * B_C * 512, IDb, nullptr, mem);
}